// round 10
// baseline (speedup 1.0000x reference)
#include <cuda_runtime.h>
#include <cuda_fp16.h>
#include <math.h>

#define MAXN 100000
#define XS 72    // W smem row stride in halves (144B -> conflict-free ldmatrix)
#define XS2 136  // concat-tile row stride in halves (272B -> conflict-free ldmatrix)

__device__ __half g_Mh[(size_t)MAXN * 64];    // fp16 messages
__device__ __half g_aggh[(size_t)MAXN * 64];  // fp16 atomic accumulation
__device__ float  g_deg[MAXN];                // in-degree

__device__ __forceinline__ unsigned smem_u32(const void* p) {
    return (unsigned)__cvta_generic_to_shared(p);
}
__device__ __forceinline__ void ldsm_x4(unsigned& r0, unsigned& r1, unsigned& r2, unsigned& r3, unsigned a) {
    asm volatile("ldmatrix.sync.aligned.m8n8.x4.shared.b16 {%0,%1,%2,%3}, [%4];"
                 : "=r"(r0), "=r"(r1), "=r"(r2), "=r"(r3) : "r"(a));
}
__device__ __forceinline__ void ldsm_x2t(unsigned& r0, unsigned& r1, unsigned a) {
    asm volatile("ldmatrix.sync.aligned.m8n8.x2.trans.shared.b16 {%0,%1}, [%2];"
                 : "=r"(r0), "=r"(r1) : "r"(a));
}
__device__ __forceinline__ void mma16816(float c[4], const unsigned a[4], unsigned b0, unsigned b1) {
    asm volatile("mma.sync.aligned.m16n8k16.row.col.f32.f16.f16.f32 "
                 "{%0,%1,%2,%3}, {%4,%5,%6,%7}, {%8,%9}, {%0,%1,%2,%3};"
                 : "+f"(c[0]), "+f"(c[1]), "+f"(c[2]), "+f"(c[3])
                 : "r"(a[0]), "r"(a[1]), "r"(a[2]), "r"(a[3]), "r"(b0), "r"(b1));
}

// ---------------------------------------------------------------------------
// Prep: g_Mh = fp16(relu(X @ W_msg + b_msg)) over a 256-row tile; also zeroes
// this block's rows of g_aggh / g_deg (ordered before scatter by the kernel
// boundary). Each warp covers two 16-row MMA tiles sharing B ldmatrix loads.
// ---------------------------------------------------------------------------
__global__ __launch_bounds__(256, 3) void k_prep(const float* __restrict__ X,
                                                 const float* __restrict__ W,
                                                 const float* __restrict__ b,
                                                 int N)
{
    __shared__ __half xs[256 * XS];   // 36,864 B
    __shared__ __half ws[64 * XS];    //  9,216 B

    int tid = threadIdx.x, lane = tid & 31, w = tid >> 5;
    int rowBase = blockIdx.x << 8;

    // stage W (64x64 f32 -> fp16)
    #pragma unroll
    for (int i = 0; i < 4; i++) {
        int idx = tid + i * 256;
        int r = idx >> 4, f = idx & 15;
        float4 v = ((const float4*)W)[idx];
        __half2 h0 = __floats2half2_rn(v.x, v.y);
        __half2 h1 = __floats2half2_rn(v.z, v.w);
        uint2 p; p.x = *(unsigned*)&h0; p.y = *(unsigned*)&h1;
        *(uint2*)&ws[r * XS + f * 4] = p;
    }
    // stage x tile (256x64): 4096 float4, 16 per thread (high MLP)
    #pragma unroll
    for (int i = 0; i < 16; i++) {
        int idx = tid + i * 256;
        int r = idx >> 4, f = idx & 15;
        int grow = rowBase + r;
        float4 v = make_float4(0.f, 0.f, 0.f, 0.f);
        if (grow < N) v = ((const float4*)(X + (size_t)grow * 64))[f];
        __half2 h0 = __floats2half2_rn(v.x, v.y);
        __half2 h1 = __floats2half2_rn(v.z, v.w);
        uint2 p; p.x = *(unsigned*)&h0; p.y = *(unsigned*)&h1;
        *(uint2*)&xs[r * XS + f * 4] = p;
    }
    // zero this block's agg rows (256 rows x 8 uint4) + deg
    {
        uint4 z = make_uint4(0u, 0u, 0u, 0u);
        #pragma unroll
        for (int i = 0; i < 8; i++) {
            int idx = tid + i * 256;
            int r = idx >> 3, f = idx & 7;
            int grow = rowBase + r;
            if (grow < N)
                *(uint4*)(g_aggh + (size_t)grow * 64 + f * 8) = z;
        }
        int grow = rowBase + tid;
        if (grow < N) g_deg[grow] = 0.f;
    }
    __syncthreads();

    int mrow = w * 16;
    unsigned A1[4][4], A2[4][4];
    #pragma unroll
    for (int kt = 0; kt < 4; kt++) {
        unsigned a1 = smem_u32(&xs[(mrow + (lane & 15)) * XS + kt * 16 + ((lane >> 4) << 3)]);
        ldsm_x4(A1[kt][0], A1[kt][1], A1[kt][2], A1[kt][3], a1);
        unsigned a2 = smem_u32(&xs[(128 + mrow + (lane & 15)) * XS + kt * 16 + ((lane >> 4) << 3)]);
        ldsm_x4(A2[kt][0], A2[kt][1], A2[kt][2], A2[kt][3], a2);
    }

    int r0 = rowBase + mrow + (lane >> 2);
    int r1 = r0 + 8;
    int r2 = r0 + 128;
    int r3 = r1 + 128;
    #pragma unroll
    for (int n = 0; n < 8; n++) {
        float c1[4] = {0.f, 0.f, 0.f, 0.f};
        float c2[4] = {0.f, 0.f, 0.f, 0.f};
        #pragma unroll
        for (int kt = 0; kt < 4; kt++) {
            unsigned b0, b1;
            unsigned addr = smem_u32(&ws[(kt * 16 + (lane & 15)) * XS + n * 8]);
            ldsm_x2t(b0, b1, addr);
            mma16816(c1, A1[kt], b0, b1);
            mma16816(c2, A2[kt], b0, b1);
        }
        int col = n * 8 + ((lane & 3) << 1);
        float bv0 = __ldg(b + col), bv1 = __ldg(b + col + 1);
        if (r0 < N) {
            __half2 h = __floats2half2_rn(fmaxf(c1[0] + bv0, 0.f), fmaxf(c1[1] + bv1, 0.f));
            *(__half2*)(g_Mh + (size_t)r0 * 64 + col) = h;
        }
        if (r1 < N) {
            __half2 h = __floats2half2_rn(fmaxf(c1[2] + bv0, 0.f), fmaxf(c1[3] + bv1, 0.f));
            *(__half2*)(g_Mh + (size_t)r1 * 64 + col) = h;
        }
        if (r2 < N) {
            __half2 h = __floats2half2_rn(fmaxf(c2[0] + bv0, 0.f), fmaxf(c2[1] + bv1, 0.f));
            *(__half2*)(g_Mh + (size_t)r2 * 64 + col) = h;
        }
        if (r3 < N) {
            __half2 h = __floats2half2_rn(fmaxf(c2[2] + bv0, 0.f), fmaxf(c2[3] + bv1, 0.f));
            *(__half2*)(g_Mh + (size_t)r3 * 64 + col) = h;
        }
    }
}

// ---------------------------------------------------------------------------
// Edge scatter: 8 lanes/edge, 4 edges/thread, fp16 v4.f16x2 reductions.
// ---------------------------------------------------------------------------
template<bool EXACT>
__global__ void k_scatter(const int* __restrict__ ei,
                          const float* __restrict__ ew, int E, int Eq)
{
    int gid = blockIdx.x * blockDim.x + threadIdx.x;
    int t = gid >> 3;
    if (t >= Eq) return;
    int g = gid & 7;

    bool has[4];
    int  src[4], dst[4];
    float w[4];
    #pragma unroll
    for (int j = 0; j < 4; j++) {
        int e = t + j * Eq;
        has[j] = EXACT ? true : (e < E);
        int ee = has[j] ? e : 0;
        src[j] = __ldg(ei + ee);
        dst[j] = __ldg(ei + E + ee);
        w[j]   = has[j] ? __ldg(ew + ee) : 0.f;
    }

    uint4 r[4];
    #pragma unroll
    for (int j = 0; j < 4; j++)
        r[j] = __ldg((const uint4*)(g_Mh + (size_t)src[j] * 64 + g * 8));

    #pragma unroll
    for (int j = 0; j < 4; j++) {
        if (!has[j]) continue;
        __half2 wh = __float2half2_rn(w[j]);
        __half2 a0 = __hmul2(*(__half2*)&r[j].x, wh);
        __half2 a1 = __hmul2(*(__half2*)&r[j].y, wh);
        __half2 a2 = __hmul2(*(__half2*)&r[j].z, wh);
        __half2 a3 = __hmul2(*(__half2*)&r[j].w, wh);
        unsigned u0 = *(unsigned*)&a0, u1 = *(unsigned*)&a1;
        unsigned u2 = *(unsigned*)&a2, u3 = *(unsigned*)&a3;
        __half* p = g_aggh + (size_t)dst[j] * 64 + g * 8;
        asm volatile("red.global.add.noftz.v4.f16x2 [%0], {%1, %2, %3, %4};"
                     :: "l"(p), "r"(u0), "r"(u1), "r"(u2), "r"(u3) : "memory");
    }

    if (g == 0) {
        #pragma unroll
        for (int j = 0; j < 4; j++) {
            if (has[j]) {
                float* dp = g_deg + dst[j];
                asm volatile("red.global.add.f32 [%0], %1;"
                             :: "l"(dp), "f"(1.0f) : "memory");
            }
        }
    }
}

// ---------------------------------------------------------------------------
// Combine (single pass, K=128 concat): h = relu([x || aggh/deg] @ W_upd + b),
// L2-normalize, write out. One staging phase, one barrier, 64 MMAs.
// ---------------------------------------------------------------------------
__global__ __launch_bounds__(256) void k_combine(const float* __restrict__ X,
                                                 const float* __restrict__ Wupd,
                                                 const float* __restrict__ b,
                                                 float* __restrict__ out, int N)
{
    __shared__ __half xs[128 * XS2];  // [node row][K=128]: cols 0..63 x, 64..127 agg
    __shared__ __half ws[128 * XS];   // full W_upd

    int tid = threadIdx.x, lane = tid & 31, w = tid >> 5;
    int rowBase = blockIdx.x << 7;

    #pragma unroll
    for (int i = 0; i < 8; i++) {
        int idx = tid + i * 256;
        int r = idx >> 4, f = idx & 15;
        float4 v = ((const float4*)Wupd)[idx];
        __half2 h0 = __floats2half2_rn(v.x, v.y);
        __half2 h1 = __floats2half2_rn(v.z, v.w);
        uint2 p; p.x = *(unsigned*)&h0; p.y = *(unsigned*)&h1;
        *(uint2*)&ws[r * XS + f * 4] = p;
    }
    #pragma unroll
    for (int i = 0; i < 8; i++) {
        int idx = tid + i * 256;
        int r = idx >> 4, f = idx & 15;
        int grow = rowBase + r;
        float4 v = make_float4(0.f, 0.f, 0.f, 0.f);
        if (grow < N) v = ((const float4*)(X + (size_t)grow * 64))[f];
        __half2 h0 = __floats2half2_rn(v.x, v.y);
        __half2 h1 = __floats2half2_rn(v.z, v.w);
        uint2 p; p.x = *(unsigned*)&h0; p.y = *(unsigned*)&h1;
        *(uint2*)&xs[r * XS2 + f * 4] = p;
    }
    #pragma unroll
    for (int i = 0; i < 8; i++) {
        int idx = tid + i * 256;
        int r = idx >> 4, f = idx & 15;
        int grow = rowBase + r;
        uint2 p = make_uint2(0u, 0u);
        if (grow < N) {
            float s = 1.0f / fmaxf(g_deg[grow], 1.0f);
            uint2 q = *(const uint2*)(g_aggh + (size_t)grow * 64 + f * 4);
            float2 f0 = __half22float2(*(__half2*)&q.x);
            float2 f1 = __half22float2(*(__half2*)&q.y);
            __half2 h0 = __floats2half2_rn(f0.x * s, f0.y * s);
            __half2 h1 = __floats2half2_rn(f1.x * s, f1.y * s);
            p.x = *(unsigned*)&h0; p.y = *(unsigned*)&h1;
        }
        *(uint2*)&xs[r * XS2 + 64 + f * 4] = p;
    }
    __syncthreads();

    int mrow = w * 16;
    unsigned A[8][4];
    #pragma unroll
    for (int kt = 0; kt < 8; kt++) {
        unsigned addr = smem_u32(&xs[(mrow + (lane & 15)) * XS2 + kt * 16 + ((lane >> 4) << 3)]);
        ldsm_x4(A[kt][0], A[kt][1], A[kt][2], A[kt][3], addr);
    }

    float c[8][4];
    #pragma unroll
    for (int n = 0; n < 8; n++)
        #pragma unroll
        for (int q = 0; q < 4; q++) c[n][q] = 0.f;

    #pragma unroll
    for (int n = 0; n < 8; n++) {
        #pragma unroll
        for (int kt = 0; kt < 8; kt++) {
            unsigned b0, b1;
            unsigned addr = smem_u32(&ws[(kt * 16 + (lane & 15)) * XS + n * 8]);
            ldsm_x2t(b0, b1, addr);
            mma16816(c[n], A[kt], b0, b1);
        }
    }

    int r0 = rowBase + mrow + (lane >> 2);
    int r1 = r0 + 8;
    float ss0 = 0.f, ss1 = 0.f;
    #pragma unroll
    for (int n = 0; n < 8; n++) {
        int col = n * 8 + ((lane & 3) << 1);
        float bv0 = __ldg(b + col), bv1 = __ldg(b + col + 1);
        float h0 = fmaxf(c[n][0] + bv0, 0.f);
        float h1 = fmaxf(c[n][1] + bv1, 0.f);
        float h2 = fmaxf(c[n][2] + bv0, 0.f);
        float h3 = fmaxf(c[n][3] + bv1, 0.f);
        c[n][0] = h0; c[n][1] = h1; c[n][2] = h2; c[n][3] = h3;
        ss0 += h0 * h0 + h1 * h1;
        ss1 += h2 * h2 + h3 * h3;
    }
    ss0 += __shfl_xor_sync(0xffffffffu, ss0, 1);
    ss0 += __shfl_xor_sync(0xffffffffu, ss0, 2);
    ss1 += __shfl_xor_sync(0xffffffffu, ss1, 1);
    ss1 += __shfl_xor_sync(0xffffffffu, ss1, 2);

    float sc0 = 1.0f / fmaxf(sqrtf(ss0), 1e-12f);
    float sc1 = 1.0f / fmaxf(sqrtf(ss1), 1e-12f);

    #pragma unroll
    for (int n = 0; n < 8; n++) {
        int col = n * 8 + ((lane & 3) << 1);
        if (r0 < N) {
            float2 v; v.x = c[n][0] * sc0; v.y = c[n][1] * sc0;
            *(float2*)(out + (size_t)r0 * 64 + col) = v;
        }
        if (r1 < N) {
            float2 v; v.x = c[n][2] * sc1; v.y = c[n][3] * sc1;
            *(float2*)(out + (size_t)r1 * 64 + col) = v;
        }
    }
}

// ---------------------------------------------------------------------------
extern "C" void kernel_launch(void* const* d_in, const int* in_sizes, int n_in,
                              void* d_out, int out_size)
{
    const float* x    = (const float*)d_in[0];
    const int*   ei   = (const int*)  d_in[1];
    const float* ew   = (const float*)d_in[2];
    const float* Wmsg = (const float*)d_in[3];
    const float* bmsg = (const float*)d_in[4];
    const float* Wupd = (const float*)d_in[5];
    const float* bupd = (const float*)d_in[6];
    float* out = (float*)d_out;

    int N = in_sizes[0] / 64;
    int E = in_sizes[2];

    int gp = (N + 255) / 256;
    k_prep<<<gp, 256>>>(x, Wmsg, bmsg, N);   // also zeroes g_aggh / g_deg

    int Eq = (E + 3) / 4;
    long long sth = (long long)Eq * 8;
    int sblocks = (int)((sth + 255) / 256);
    if ((E & 3) == 0)
        k_scatter<true><<<sblocks, 256>>>(ei, ew, E, Eq);
    else
        k_scatter<false><<<sblocks, 256>>>(ei, ew, E, Eq);

    int gb = (N + 127) / 128;
    k_combine<<<gb, 256>>>(x, Wupd, bupd, out, N);
}

// round 11
// speedup vs baseline: 1.0168x; 1.0168x over previous
#include <cuda_runtime.h>
#include <cuda_fp16.h>
#include <math.h>

#define MAXN 100000
#define XS 72    // W smem row stride in halves (144B -> conflict-free ldmatrix)
#define XS2 136  // concat-tile row stride in halves (272B -> conflict-free ldmatrix)

__device__ __half g_Mh[(size_t)MAXN * 64];    // fp16 messages
__device__ __half g_aggh[(size_t)MAXN * 64];  // fp16 atomic accumulation
__device__ float  g_deg[MAXN];                // in-degree

__device__ __forceinline__ unsigned smem_u32(const void* p) {
    return (unsigned)__cvta_generic_to_shared(p);
}
__device__ __forceinline__ void ldsm_x4(unsigned& r0, unsigned& r1, unsigned& r2, unsigned& r3, unsigned a) {
    asm volatile("ldmatrix.sync.aligned.m8n8.x4.shared.b16 {%0,%1,%2,%3}, [%4];"
                 : "=r"(r0), "=r"(r1), "=r"(r2), "=r"(r3) : "r"(a));
}
__device__ __forceinline__ void ldsm_x2t(unsigned& r0, unsigned& r1, unsigned a) {
    asm volatile("ldmatrix.sync.aligned.m8n8.x2.trans.shared.b16 {%0,%1}, [%2];"
                 : "=r"(r0), "=r"(r1) : "r"(a));
}
__device__ __forceinline__ void mma16816(float c[4], const unsigned a[4], unsigned b0, unsigned b1) {
    asm volatile("mma.sync.aligned.m16n8k16.row.col.f32.f16.f16.f32 "
                 "{%0,%1,%2,%3}, {%4,%5,%6,%7}, {%8,%9}, {%0,%1,%2,%3};"
                 : "+f"(c[0]), "+f"(c[1]), "+f"(c[2]), "+f"(c[3])
                 : "r"(a[0]), "r"(a[1]), "r"(a[2]), "r"(a[3]), "r"(b0), "r"(b1));
}

// ---------------------------------------------------------------------------
// Prep: g_Mh = fp16(relu(X @ W_msg + b_msg)) over a 256-row tile; also zeroes
// this block's rows of g_aggh / g_deg (ordered before scatter by the kernel
// boundary). Each warp covers two 16-row MMA tiles sharing B ldmatrix loads.
// ---------------------------------------------------------------------------
__global__ __launch_bounds__(256, 3) void k_prep(const float* __restrict__ X,
                                                 const float* __restrict__ W,
                                                 const float* __restrict__ b,
                                                 int N)
{
    __shared__ __half xs[256 * XS];   // 36,864 B
    __shared__ __half ws[64 * XS];    //  9,216 B

    int tid = threadIdx.x, lane = tid & 31, w = tid >> 5;
    int rowBase = blockIdx.x << 8;

    // stage W (64x64 f32 -> fp16)
    #pragma unroll
    for (int i = 0; i < 4; i++) {
        int idx = tid + i * 256;
        int r = idx >> 4, f = idx & 15;
        float4 v = ((const float4*)W)[idx];
        __half2 h0 = __floats2half2_rn(v.x, v.y);
        __half2 h1 = __floats2half2_rn(v.z, v.w);
        uint2 p; p.x = *(unsigned*)&h0; p.y = *(unsigned*)&h1;
        *(uint2*)&ws[r * XS + f * 4] = p;
    }
    // stage x tile (256x64): 4096 float4, 16 per thread (high MLP)
    #pragma unroll
    for (int i = 0; i < 16; i++) {
        int idx = tid + i * 256;
        int r = idx >> 4, f = idx & 15;
        int grow = rowBase + r;
        float4 v = make_float4(0.f, 0.f, 0.f, 0.f);
        if (grow < N) v = ((const float4*)(X + (size_t)grow * 64))[f];
        __half2 h0 = __floats2half2_rn(v.x, v.y);
        __half2 h1 = __floats2half2_rn(v.z, v.w);
        uint2 p; p.x = *(unsigned*)&h0; p.y = *(unsigned*)&h1;
        *(uint2*)&xs[r * XS + f * 4] = p;
    }
    // zero this block's agg rows (256 rows x 8 uint4) + deg
    {
        uint4 z = make_uint4(0u, 0u, 0u, 0u);
        #pragma unroll
        for (int i = 0; i < 8; i++) {
            int idx = tid + i * 256;
            int r = idx >> 3, f = idx & 7;
            int grow = rowBase + r;
            if (grow < N)
                *(uint4*)(g_aggh + (size_t)grow * 64 + f * 8) = z;
        }
        int grow = rowBase + tid;
        if (grow < N) g_deg[grow] = 0.f;
    }
    __syncthreads();

    int mrow = w * 16;
    unsigned A1[4][4], A2[4][4];
    #pragma unroll
    for (int kt = 0; kt < 4; kt++) {
        unsigned a1 = smem_u32(&xs[(mrow + (lane & 15)) * XS + kt * 16 + ((lane >> 4) << 3)]);
        ldsm_x4(A1[kt][0], A1[kt][1], A1[kt][2], A1[kt][3], a1);
        unsigned a2 = smem_u32(&xs[(128 + mrow + (lane & 15)) * XS + kt * 16 + ((lane >> 4) << 3)]);
        ldsm_x4(A2[kt][0], A2[kt][1], A2[kt][2], A2[kt][3], a2);
    }

    int r0 = rowBase + mrow + (lane >> 2);
    int r1 = r0 + 8;
    int r2 = r0 + 128;
    int r3 = r1 + 128;
    #pragma unroll
    for (int n = 0; n < 8; n++) {
        float c1[4] = {0.f, 0.f, 0.f, 0.f};
        float c2[4] = {0.f, 0.f, 0.f, 0.f};
        #pragma unroll
        for (int kt = 0; kt < 4; kt++) {
            unsigned b0, b1;
            unsigned addr = smem_u32(&ws[(kt * 16 + (lane & 15)) * XS + n * 8]);
            ldsm_x2t(b0, b1, addr);
            mma16816(c1, A1[kt], b0, b1);
            mma16816(c2, A2[kt], b0, b1);
        }
        int col = n * 8 + ((lane & 3) << 1);
        float bv0 = __ldg(b + col), bv1 = __ldg(b + col + 1);
        if (r0 < N) {
            __half2 h = __floats2half2_rn(fmaxf(c1[0] + bv0, 0.f), fmaxf(c1[1] + bv1, 0.f));
            *(__half2*)(g_Mh + (size_t)r0 * 64 + col) = h;
        }
        if (r1 < N) {
            __half2 h = __floats2half2_rn(fmaxf(c1[2] + bv0, 0.f), fmaxf(c1[3] + bv1, 0.f));
            *(__half2*)(g_Mh + (size_t)r1 * 64 + col) = h;
        }
        if (r2 < N) {
            __half2 h = __floats2half2_rn(fmaxf(c2[0] + bv0, 0.f), fmaxf(c2[1] + bv1, 0.f));
            *(__half2*)(g_Mh + (size_t)r2 * 64 + col) = h;
        }
        if (r3 < N) {
            __half2 h = __floats2half2_rn(fmaxf(c2[2] + bv0, 0.f), fmaxf(c2[3] + bv1, 0.f));
            *(__half2*)(g_Mh + (size_t)r3 * 64 + col) = h;
        }
    }
}

// ---------------------------------------------------------------------------
// Edge scatter: 8 lanes/edge, 4 edges/thread, fp16 v4.f16x2 reductions.
// ---------------------------------------------------------------------------
template<bool EXACT>
__global__ void k_scatter(const int* __restrict__ ei,
                          const float* __restrict__ ew, int E, int Eq)
{
    int gid = blockIdx.x * blockDim.x + threadIdx.x;
    int t = gid >> 3;
    if (t >= Eq) return;
    int g = gid & 7;

    bool has[4];
    int  src[4], dst[4];
    float w[4];
    #pragma unroll
    for (int j = 0; j < 4; j++) {
        int e = t + j * Eq;
        has[j] = EXACT ? true : (e < E);
        int ee = has[j] ? e : 0;
        src[j] = __ldg(ei + ee);
        dst[j] = __ldg(ei + E + ee);
        w[j]   = has[j] ? __ldg(ew + ee) : 0.f;
    }

    uint4 r[4];
    #pragma unroll
    for (int j = 0; j < 4; j++)
        r[j] = __ldg((const uint4*)(g_Mh + (size_t)src[j] * 64 + g * 8));

    #pragma unroll
    for (int j = 0; j < 4; j++) {
        if (!has[j]) continue;
        __half2 wh = __float2half2_rn(w[j]);
        __half2 a0 = __hmul2(*(__half2*)&r[j].x, wh);
        __half2 a1 = __hmul2(*(__half2*)&r[j].y, wh);
        __half2 a2 = __hmul2(*(__half2*)&r[j].z, wh);
        __half2 a3 = __hmul2(*(__half2*)&r[j].w, wh);
        unsigned u0 = *(unsigned*)&a0, u1 = *(unsigned*)&a1;
        unsigned u2 = *(unsigned*)&a2, u3 = *(unsigned*)&a3;
        __half* p = g_aggh + (size_t)dst[j] * 64 + g * 8;
        asm volatile("red.global.add.noftz.v4.f16x2 [%0], {%1, %2, %3, %4};"
                     :: "l"(p), "r"(u0), "r"(u1), "r"(u2), "r"(u3) : "memory");
    }

    if (g == 0) {
        #pragma unroll
        for (int j = 0; j < 4; j++) {
            if (has[j]) {
                float* dp = g_deg + dst[j];
                asm volatile("red.global.add.f32 [%0], %1;"
                             :: "l"(dp), "f"(1.0f) : "memory");
            }
        }
    }
}

// ---------------------------------------------------------------------------
// Combine (single pass, K=128 concat): h = relu([x || aggh/deg] @ W_upd + b),
// L2-normalize, write out. One staging phase, one barrier, 64 MMAs.
// ---------------------------------------------------------------------------
__global__ __launch_bounds__(256) void k_combine(const float* __restrict__ X,
                                                 const float* __restrict__ Wupd,
                                                 const float* __restrict__ b,
                                                 float* __restrict__ out, int N)
{
    __shared__ __half xs[128 * XS2];  // [node row][K=128]: cols 0..63 x, 64..127 agg
    __shared__ __half ws[128 * XS];   // full W_upd

    int tid = threadIdx.x, lane = tid & 31, w = tid >> 5;
    int rowBase = blockIdx.x << 7;

    #pragma unroll
    for (int i = 0; i < 8; i++) {
        int idx = tid + i * 256;
        int r = idx >> 4, f = idx & 15;
        float4 v = ((const float4*)Wupd)[idx];
        __half2 h0 = __floats2half2_rn(v.x, v.y);
        __half2 h1 = __floats2half2_rn(v.z, v.w);
        uint2 p; p.x = *(unsigned*)&h0; p.y = *(unsigned*)&h1;
        *(uint2*)&ws[r * XS + f * 4] = p;
    }
    #pragma unroll
    for (int i = 0; i < 8; i++) {
        int idx = tid + i * 256;
        int r = idx >> 4, f = idx & 15;
        int grow = rowBase + r;
        float4 v = make_float4(0.f, 0.f, 0.f, 0.f);
        if (grow < N) v = ((const float4*)(X + (size_t)grow * 64))[f];
        __half2 h0 = __floats2half2_rn(v.x, v.y);
        __half2 h1 = __floats2half2_rn(v.z, v.w);
        uint2 p; p.x = *(unsigned*)&h0; p.y = *(unsigned*)&h1;
        *(uint2*)&xs[r * XS2 + f * 4] = p;
    }
    #pragma unroll
    for (int i = 0; i < 8; i++) {
        int idx = tid + i * 256;
        int r = idx >> 4, f = idx & 15;
        int grow = rowBase + r;
        uint2 p = make_uint2(0u, 0u);
        if (grow < N) {
            float s = 1.0f / fmaxf(g_deg[grow], 1.0f);
            uint2 q = *(const uint2*)(g_aggh + (size_t)grow * 64 + f * 4);
            float2 f0 = __half22float2(*(__half2*)&q.x);
            float2 f1 = __half22float2(*(__half2*)&q.y);
            __half2 h0 = __floats2half2_rn(f0.x * s, f0.y * s);
            __half2 h1 = __floats2half2_rn(f1.x * s, f1.y * s);
            p.x = *(unsigned*)&h0; p.y = *(unsigned*)&h1;
        }
        *(uint2*)&xs[r * XS2 + 64 + f * 4] = p;
    }
    __syncthreads();

    int mrow = w * 16;
    unsigned A[8][4];
    #pragma unroll
    for (int kt = 0; kt < 8; kt++) {
        unsigned addr = smem_u32(&xs[(mrow + (lane & 15)) * XS2 + kt * 16 + ((lane >> 4) << 3)]);
        ldsm_x4(A[kt][0], A[kt][1], A[kt][2], A[kt][3], addr);
    }

    float c[8][4];
    #pragma unroll
    for (int n = 0; n < 8; n++)
        #pragma unroll
        for (int q = 0; q < 4; q++) c[n][q] = 0.f;

    #pragma unroll
    for (int n = 0; n < 8; n++) {
        #pragma unroll
        for (int kt = 0; kt < 8; kt++) {
            unsigned b0, b1;
            unsigned addr = smem_u32(&ws[(kt * 16 + (lane & 15)) * XS + n * 8]);
            ldsm_x2t(b0, b1, addr);
            mma16816(c[n], A[kt], b0, b1);
        }
    }

    int r0 = rowBase + mrow + (lane >> 2);
    int r1 = r0 + 8;
    float ss0 = 0.f, ss1 = 0.f;
    #pragma unroll
    for (int n = 0; n < 8; n++) {
        int col = n * 8 + ((lane & 3) << 1);
        float bv0 = __ldg(b + col), bv1 = __ldg(b + col + 1);
        float h0 = fmaxf(c[n][0] + bv0, 0.f);
        float h1 = fmaxf(c[n][1] + bv1, 0.f);
        float h2 = fmaxf(c[n][2] + bv0, 0.f);
        float h3 = fmaxf(c[n][3] + bv1, 0.f);
        c[n][0] = h0; c[n][1] = h1; c[n][2] = h2; c[n][3] = h3;
        ss0 += h0 * h0 + h1 * h1;
        ss1 += h2 * h2 + h3 * h3;
    }
    ss0 += __shfl_xor_sync(0xffffffffu, ss0, 1);
    ss0 += __shfl_xor_sync(0xffffffffu, ss0, 2);
    ss1 += __shfl_xor_sync(0xffffffffu, ss1, 1);
    ss1 += __shfl_xor_sync(0xffffffffu, ss1, 2);

    float sc0 = 1.0f / fmaxf(sqrtf(ss0), 1e-12f);
    float sc1 = 1.0f / fmaxf(sqrtf(ss1), 1e-12f);

    #pragma unroll
    for (int n = 0; n < 8; n++) {
        int col = n * 8 + ((lane & 3) << 1);
        if (r0 < N) {
            float2 v; v.x = c[n][0] * sc0; v.y = c[n][1] * sc0;
            *(float2*)(out + (size_t)r0 * 64 + col) = v;
        }
        if (r1 < N) {
            float2 v; v.x = c[n][2] * sc1; v.y = c[n][3] * sc1;
            *(float2*)(out + (size_t)r1 * 64 + col) = v;
        }
    }
}

// ---------------------------------------------------------------------------
extern "C" void kernel_launch(void* const* d_in, const int* in_sizes, int n_in,
                              void* d_out, int out_size)
{
    const float* x    = (const float*)d_in[0];
    const int*   ei   = (const int*)  d_in[1];
    const float* ew   = (const float*)d_in[2];
    const float* Wmsg = (const float*)d_in[3];
    const float* bmsg = (const float*)d_in[4];
    const float* Wupd = (const float*)d_in[5];
    const float* bupd = (const float*)d_in[6];
    float* out = (float*)d_out;

    int N = in_sizes[0] / 64;
    int E = in_sizes[2];

    int gp = (N + 255) / 256;
    k_prep<<<gp, 256>>>(x, Wmsg, bmsg, N);   // also zeroes g_aggh / g_deg

    int Eq = (E + 3) / 4;
    long long sth = (long long)Eq * 8;
    int sblocks = (int)((sth + 255) / 256);
    if ((E & 3) == 0)
        k_scatter<true><<<sblocks, 256>>>(ei, ew, E, Eq);
    else
        k_scatter<false><<<sblocks, 256>>>(ei, ew, E, Eq);

    int gb = (N + 127) / 128;
    k_combine<<<gb, 256>>>(x, Wupd, bupd, out, N);
}

// round 12
// speedup vs baseline: 1.1311x; 1.1124x over previous
#include <cuda_runtime.h>
#include <cuda_fp16.h>
#include <math.h>

#define MAXN 100000
#define XS 72    // W smem row stride in halves (144B -> conflict-free ldmatrix)
#define XS2 136  // concat-tile row stride in halves (272B -> conflict-free ldmatrix)

__device__ __half g_Mh[(size_t)MAXN * 64];    // fp16 messages
__device__ __half g_aggh[(size_t)MAXN * 64];  // fp16 atomic accumulation
__device__ float  g_deg[MAXN];                // in-degree

__device__ __forceinline__ unsigned smem_u32(const void* p) {
    return (unsigned)__cvta_generic_to_shared(p);
}
__device__ __forceinline__ void ldsm_x4(unsigned& r0, unsigned& r1, unsigned& r2, unsigned& r3, unsigned a) {
    asm volatile("ldmatrix.sync.aligned.m8n8.x4.shared.b16 {%0,%1,%2,%3}, [%4];"
                 : "=r"(r0), "=r"(r1), "=r"(r2), "=r"(r3) : "r"(a));
}
__device__ __forceinline__ void ldsm_x2t(unsigned& r0, unsigned& r1, unsigned a) {
    asm volatile("ldmatrix.sync.aligned.m8n8.x2.trans.shared.b16 {%0,%1}, [%2];"
                 : "=r"(r0), "=r"(r1) : "r"(a));
}
__device__ __forceinline__ void mma16816(float c[4], const unsigned a[4], unsigned b0, unsigned b1) {
    asm volatile("mma.sync.aligned.m16n8k16.row.col.f32.f16.f16.f32 "
                 "{%0,%1,%2,%3}, {%4,%5,%6,%7}, {%8,%9}, {%0,%1,%2,%3};"
                 : "+f"(c[0]), "+f"(c[1]), "+f"(c[2]), "+f"(c[3])
                 : "r"(a[0]), "r"(a[1]), "r"(a[2]), "r"(a[3]), "r"(b0), "r"(b1));
}
__device__ __forceinline__ unsigned hmul2u(unsigned a, __half2 s) {
    __half2 v = __hmul2(*(__half2*)&a, s);
    return *(unsigned*)&v;
}

// ---------------------------------------------------------------------------
// Prep: g_Mh = fp16(relu(X @ W_msg + b_msg)); 128-row tile (R9 version);
// also zeroes this block's rows of g_aggh / g_deg.
// ---------------------------------------------------------------------------
__global__ __launch_bounds__(256) void k_prep(const float* __restrict__ X,
                                              const float* __restrict__ W,
                                              const float* __restrict__ b,
                                              int N)
{
    __shared__ __half xs[128 * XS];
    __shared__ __half ws[64 * XS];

    int tid = threadIdx.x, lane = tid & 31, w = tid >> 5;
    int rowBase = blockIdx.x << 7;

    #pragma unroll
    for (int i = 0; i < 4; i++) {
        int idx = tid + i * 256;
        int r = idx >> 4, f = idx & 15;
        float4 v = ((const float4*)W)[idx];
        __half2 h0 = __floats2half2_rn(v.x, v.y);
        __half2 h1 = __floats2half2_rn(v.z, v.w);
        uint2 p; p.x = *(unsigned*)&h0; p.y = *(unsigned*)&h1;
        *(uint2*)&ws[r * XS + f * 4] = p;
    }
    #pragma unroll
    for (int i = 0; i < 8; i++) {
        int idx = tid + i * 256;
        int r = idx >> 4, f = idx & 15;
        int grow = rowBase + r;
        float4 v = make_float4(0.f, 0.f, 0.f, 0.f);
        if (grow < N) v = ((const float4*)(X + (size_t)grow * 64))[f];
        __half2 h0 = __floats2half2_rn(v.x, v.y);
        __half2 h1 = __floats2half2_rn(v.z, v.w);
        uint2 p; p.x = *(unsigned*)&h0; p.y = *(unsigned*)&h1;
        *(uint2*)&xs[r * XS + f * 4] = p;
    }
    // zero this block's agg rows + deg
    {
        uint4 z = make_uint4(0u, 0u, 0u, 0u);
        #pragma unroll
        for (int i = 0; i < 4; i++) {
            int idx = tid + i * 256;
            int r = idx >> 3, f = idx & 7;
            int grow = rowBase + r;
            if (grow < N)
                *(uint4*)(g_aggh + (size_t)grow * 64 + f * 8) = z;
        }
        int grow = rowBase + tid;
        if (tid < 128 && grow < N) g_deg[grow] = 0.f;
    }
    __syncthreads();

    int mrow = w * 16;
    unsigned A[4][4];
    #pragma unroll
    for (int kt = 0; kt < 4; kt++) {
        unsigned addr = smem_u32(&xs[(mrow + (lane & 15)) * XS + kt * 16 + ((lane >> 4) << 3)]);
        ldsm_x4(A[kt][0], A[kt][1], A[kt][2], A[kt][3], addr);
    }

    int r0 = rowBase + mrow + (lane >> 2);
    int r1 = r0 + 8;
    #pragma unroll
    for (int n = 0; n < 8; n++) {
        float c[4] = {0.f, 0.f, 0.f, 0.f};
        #pragma unroll
        for (int kt = 0; kt < 4; kt++) {
            unsigned b0, b1;
            unsigned addr = smem_u32(&ws[(kt * 16 + (lane & 15)) * XS + n * 8]);
            ldsm_x2t(b0, b1, addr);
            mma16816(c, A[kt], b0, b1);
        }
        int col = n * 8 + ((lane & 3) << 1);
        float bv0 = __ldg(b + col), bv1 = __ldg(b + col + 1);
        if (r0 < N) {
            __half2 h = __floats2half2_rn(fmaxf(c[0] + bv0, 0.f), fmaxf(c[1] + bv1, 0.f));
            *(__half2*)(g_Mh + (size_t)r0 * 64 + col) = h;
        }
        if (r1 < N) {
            __half2 h = __floats2half2_rn(fmaxf(c[2] + bv0, 0.f), fmaxf(c[3] + bv1, 0.f));
            *(__half2*)(g_Mh + (size_t)r1 * 64 + col) = h;
        }
    }
}

// ---------------------------------------------------------------------------
// Edge scatter: 8 lanes/edge, 4 edges/thread, fp16 v4.f16x2 reductions.
// ---------------------------------------------------------------------------
template<bool EXACT>
__global__ void k_scatter(const int* __restrict__ ei,
                          const float* __restrict__ ew, int E, int Eq)
{
    int gid = blockIdx.x * blockDim.x + threadIdx.x;
    int t = gid >> 3;
    if (t >= Eq) return;
    int g = gid & 7;

    bool has[4];
    int  src[4], dst[4];
    float w[4];
    #pragma unroll
    for (int j = 0; j < 4; j++) {
        int e = t + j * Eq;
        has[j] = EXACT ? true : (e < E);
        int ee = has[j] ? e : 0;
        src[j] = __ldg(ei + ee);
        dst[j] = __ldg(ei + E + ee);
        w[j]   = has[j] ? __ldg(ew + ee) : 0.f;
    }

    uint4 r[4];
    #pragma unroll
    for (int j = 0; j < 4; j++)
        r[j] = __ldg((const uint4*)(g_Mh + (size_t)src[j] * 64 + g * 8));

    #pragma unroll
    for (int j = 0; j < 4; j++) {
        if (!has[j]) continue;
        __half2 wh = __float2half2_rn(w[j]);
        __half2 a0 = __hmul2(*(__half2*)&r[j].x, wh);
        __half2 a1 = __hmul2(*(__half2*)&r[j].y, wh);
        __half2 a2 = __hmul2(*(__half2*)&r[j].z, wh);
        __half2 a3 = __hmul2(*(__half2*)&r[j].w, wh);
        unsigned u0 = *(unsigned*)&a0, u1 = *(unsigned*)&a1;
        unsigned u2 = *(unsigned*)&a2, u3 = *(unsigned*)&a3;
        __half* p = g_aggh + (size_t)dst[j] * 64 + g * 8;
        asm volatile("red.global.add.noftz.v4.f16x2 [%0], {%1, %2, %3, %4};"
                     :: "l"(p), "r"(u0), "r"(u1), "r"(u2), "r"(u3) : "memory");
    }

    if (g == 0) {
        #pragma unroll
        for (int j = 0; j < 4; j++) {
            if (has[j]) {
                float* dp = g_deg + dst[j];
                asm volatile("red.global.add.f32 [%0], %1;"
                             :: "l"(dp), "f"(1.0f) : "memory");
            }
        }
    }
}

// ---------------------------------------------------------------------------
// Combine (single pass, K=128 concat): h = relu([x || aggh/deg] @ W_upd + b),
// L2-normalize, write out. agg staged RAW (16B copies); deg scaling applied
// to the A fragments (kt 4..7) after ldmatrix via HMUL2.
// ---------------------------------------------------------------------------
__global__ __launch_bounds__(256) void k_combine(const float* __restrict__ X,
                                                 const float* __restrict__ Wupd,
                                                 const float* __restrict__ b,
                                                 float* __restrict__ out, int N)
{
    __shared__ __half xs[128 * XS2];  // [node row][K=128]: cols 0..63 x, 64..127 agg
    __shared__ __half ws[128 * XS];   // full W_upd

    int tid = threadIdx.x, lane = tid & 31, w = tid >> 5;
    int rowBase = blockIdx.x << 7;

    // stage full W_upd
    #pragma unroll
    for (int i = 0; i < 8; i++) {
        int idx = tid + i * 256;
        int r = idx >> 4, f = idx & 15;
        float4 v = ((const float4*)Wupd)[idx];
        __half2 h0 = __floats2half2_rn(v.x, v.y);
        __half2 h1 = __floats2half2_rn(v.z, v.w);
        uint2 p; p.x = *(unsigned*)&h0; p.y = *(unsigned*)&h1;
        *(uint2*)&ws[r * XS + f * 4] = p;
    }
    // stage x -> cols 0..63 (f32 -> fp16)
    #pragma unroll
    for (int i = 0; i < 8; i++) {
        int idx = tid + i * 256;
        int r = idx >> 4, f = idx & 15;
        int grow = rowBase + r;
        float4 v = make_float4(0.f, 0.f, 0.f, 0.f);
        if (grow < N) v = ((const float4*)(X + (size_t)grow * 64))[f];
        __half2 h0 = __floats2half2_rn(v.x, v.y);
        __half2 h1 = __floats2half2_rn(v.z, v.w);
        uint2 p; p.x = *(unsigned*)&h0; p.y = *(unsigned*)&h1;
        *(uint2*)&xs[r * XS2 + f * 4] = p;
    }
    // stage aggh RAW -> cols 64..127 (pure 16B copies)
    #pragma unroll
    for (int i = 0; i < 4; i++) {
        int idx = tid + i * 256;
        int r = idx >> 3, f = idx & 7;    // 8 uint4 per 64-half row
        int grow = rowBase + r;
        uint4 q = make_uint4(0u, 0u, 0u, 0u);
        if (grow < N) q = *(const uint4*)(g_aggh + (size_t)grow * 64 + f * 8);
        *(uint4*)&xs[r * XS2 + 64 + f * 8] = q;
    }
    __syncthreads();

    int mrow = w * 16;
    int r0 = rowBase + mrow + (lane >> 2);
    int r1 = r0 + 8;

    // per-row inverse degree (fp16 scale applied to agg A-fragments)
    float d0 = (r0 < N) ? g_deg[r0] : 1.f;
    float d1 = (r1 < N) ? g_deg[r1] : 1.f;
    __half2 s0 = __float2half2_rn(1.0f / fmaxf(d0, 1.0f));
    __half2 s1 = __float2half2_rn(1.0f / fmaxf(d1, 1.0f));

    unsigned A[8][4];
    #pragma unroll
    for (int kt = 0; kt < 8; kt++) {
        unsigned addr = smem_u32(&xs[(mrow + (lane & 15)) * XS2 + kt * 16 + ((lane >> 4) << 3)]);
        ldsm_x4(A[kt][0], A[kt][1], A[kt][2], A[kt][3], addr);
    }
    // scale agg fragments: regs {0,2} belong to row r0, regs {1,3} to row r1
    #pragma unroll
    for (int kt = 4; kt < 8; kt++) {
        A[kt][0] = hmul2u(A[kt][0], s0);
        A[kt][1] = hmul2u(A[kt][1], s1);
        A[kt][2] = hmul2u(A[kt][2], s0);
        A[kt][3] = hmul2u(A[kt][3], s1);
    }

    float c[8][4];
    #pragma unroll
    for (int n = 0; n < 8; n++)
        #pragma unroll
        for (int q = 0; q < 4; q++) c[n][q] = 0.f;

    #pragma unroll
    for (int n = 0; n < 8; n++) {
        #pragma unroll
        for (int kt = 0; kt < 8; kt++) {
            unsigned b0, b1;
            unsigned addr = smem_u32(&ws[(kt * 16 + (lane & 15)) * XS + n * 8]);
            ldsm_x2t(b0, b1, addr);
            mma16816(c[n], A[kt], b0, b1);
        }
    }

    // epilogue: +bias, relu, row norms via shfl
    float ss0 = 0.f, ss1 = 0.f;
    #pragma unroll
    for (int n = 0; n < 8; n++) {
        int col = n * 8 + ((lane & 3) << 1);
        float bv0 = __ldg(b + col), bv1 = __ldg(b + col + 1);
        float h0 = fmaxf(c[n][0] + bv0, 0.f);
        float h1 = fmaxf(c[n][1] + bv1, 0.f);
        float h2 = fmaxf(c[n][2] + bv0, 0.f);
        float h3 = fmaxf(c[n][3] + bv1, 0.f);
        c[n][0] = h0; c[n][1] = h1; c[n][2] = h2; c[n][3] = h3;
        ss0 += h0 * h0 + h1 * h1;
        ss1 += h2 * h2 + h3 * h3;
    }
    ss0 += __shfl_xor_sync(0xffffffffu, ss0, 1);
    ss0 += __shfl_xor_sync(0xffffffffu, ss0, 2);
    ss1 += __shfl_xor_sync(0xffffffffu, ss1, 1);
    ss1 += __shfl_xor_sync(0xffffffffu, ss1, 2);

    float sc0 = 1.0f / fmaxf(sqrtf(ss0), 1e-12f);
    float sc1 = 1.0f / fmaxf(sqrtf(ss1), 1e-12f);

    #pragma unroll
    for (int n = 0; n < 8; n++) {
        int col = n * 8 + ((lane & 3) << 1);
        if (r0 < N) {
            float2 v; v.x = c[n][0] * sc0; v.y = c[n][1] * sc0;
            *(float2*)(out + (size_t)r0 * 64 + col) = v;
        }
        if (r1 < N) {
            float2 v; v.x = c[n][2] * sc1; v.y = c[n][3] * sc1;
            *(float2*)(out + (size_t)r1 * 64 + col) = v;
        }
    }
}

// ---------------------------------------------------------------------------
extern "C" void kernel_launch(void* const* d_in, const int* in_sizes, int n_in,
                              void* d_out, int out_size)
{
    const float* x    = (const float*)d_in[0];
    const int*   ei   = (const int*)  d_in[1];
    const float* ew   = (const float*)d_in[2];
    const float* Wmsg = (const float*)d_in[3];
    const float* bmsg = (const float*)d_in[4];
    const float* Wupd = (const float*)d_in[5];
    const float* bupd = (const float*)d_in[6];
    float* out = (float*)d_out;

    int N = in_sizes[0] / 64;
    int E = in_sizes[2];

    int gb = (N + 127) / 128;
    k_prep<<<gb, 256>>>(x, Wmsg, bmsg, N);   // also zeroes g_aggh / g_deg

    int Eq = (E + 3) / 4;
    long long sth = (long long)Eq * 8;
    int sblocks = (int)((sth + 255) / 256);
    if ((E & 3) == 0)
        k_scatter<true><<<sblocks, 256>>>(ei, ew, E, Eq);
    else
        k_scatter<false><<<sblocks, 256>>>(ei, ew, E, Eq);

    k_combine<<<gb, 256>>>(x, Wupd, bupd, out, N);
}